// round 14
// baseline (speedup 1.0000x reference)
#include <cuda_runtime.h>

#define Bx 16
#define NN 256
#define MM 256
#define DD 256
#define UU 256

typedef unsigned long long u64;

// scratch (device globals — no allocations allowed)
__device__ float g_encpT[Bx * UU * MM];  // enc_proj TRANSPOSED [B][U][M]
__device__ float g_decp [Bx * NN * UU];  // dec_proj [B][N][U]

__device__ __forceinline__ float tanh_ap(float x) {
    float y;
    asm("tanh.approx.f32 %0, %1;" : "=f"(y) : "f"(x));
    return y;
}
__device__ __forceinline__ u64 pk2(float lo, float hi) {
    u64 r;
    asm("mov.b64 %0, {%1, %2};" : "=l"(r) : "f"(lo), "f"(hi));
    return r;
}
__device__ __forceinline__ void upk2(u64 v, float& lo, float& hi) {
    asm("mov.b64 {%0, %1}, %2;" : "=f"(lo), "=f"(hi) : "l"(v));
}
__device__ __forceinline__ u64 ffma2(u64 a, u64 b, u64 c) {
    u64 d;
    asm("fma.rn.f32x2 %0, %1, %2, %3;" : "=l"(d) : "l"(a), "l"(b), "l"(c));
    return d;
}
__device__ __forceinline__ void cpa16(void* smem_dst, const void* gsrc) {
    unsigned sa = (unsigned)__cvta_generic_to_shared(smem_dst);
    asm volatile("cp.async.cg.shared.global [%0], [%1], 16;" :: "r"(sa), "l"(gsrc));
}
#define CPA_COMMIT asm volatile("cp.async.commit_group;")
#define CPA_WAIT1  asm volatile("cp.async.wait_group 1;")

// ---------------------------------------------------------------------------
// Projection GEMM (R7 version — proven): 128x128 tile, 256 threads, 8x8
// microtile, f32x2 FMA, cp.async double-buffered BK=16. Grid (2,32,2).
// z=0: enc@W1+b1 -> g_encpT (transposed [B,U,M]); z=1: dec@W2+b2 -> g_decp.
// ---------------------------------------------------------------------------
__global__ __launch_bounds__(256) void proj_gemm(const float* __restrict__ enc,
                                                 const float* __restrict__ dec,
                                                 const float* __restrict__ W1,
                                                 const float* __restrict__ b1,
                                                 const float* __restrict__ W2,
                                                 const float* __restrict__ b2)
{
    const int z = blockIdx.z;
    const float* A    = z ? dec : enc;
    const float* W    = z ? W2  : W1;
    const float* bias = z ? b2  : b1;

    __shared__ float As[2][128 * 20];
    __shared__ float Ws[2][16 * 128];

    const int tid = threadIdx.x;
    const int ty = tid >> 4;
    const int tx = tid & 15;
    const int row0 = blockIdx.y * 128;
    const int col0 = blockIdx.x * 128;

    u64 acc[8][4] = {};

    #define PROJ_PREF(kt, bi)                                                   \
        {                                                                       \
            _Pragma("unroll")                                                   \
            for (int i = 0; i < 2; i++) {                                       \
                int fid = tid * 2 + i;                                          \
                int r = fid >> 2, kg = fid & 3;                                 \
                cpa16(&As[bi][r * 20 + kg * 4],                                 \
                      A + (size_t)(row0 + r) * 256 + (kt) + kg * 4);            \
            }                                                                   \
            _Pragma("unroll")                                                   \
            for (int i = 0; i < 2; i++) {                                       \
                int fid = tid * 2 + i;                                          \
                int k = fid >> 5, c4 = fid & 31;                                \
                cpa16(&Ws[bi][k * 128 + c4 * 4],                                \
                      W + (size_t)((kt) + k) * 256 + col0 + c4 * 4);            \
            }                                                                   \
        }

    PROJ_PREF(0, 0);
    CPA_COMMIT;
    for (int t16 = 0; t16 < 16; t16++) {
        if (t16 + 1 < 16) PROJ_PREF((t16 + 1) * 16, (t16 + 1) & 1);
        CPA_COMMIT;
        CPA_WAIT1;
        __syncthreads();
        const float* as = As[t16 & 1];
        const float* ws = Ws[t16 & 1];
        #pragma unroll
        for (int k = 0; k < 16; k++) {
            float4 wlo = *(const float4*)(ws + k * 128 + tx * 4);
            float4 whi = *(const float4*)(ws + k * 128 + 64 + tx * 4);
            u64 w0 = pk2(wlo.x, wlo.y);
            u64 w1 = pk2(wlo.z, wlo.w);
            u64 w2 = pk2(whi.x, whi.y);
            u64 w3 = pk2(whi.z, whi.w);
            #pragma unroll
            for (int ri = 0; ri < 8; ri++) {
                int r = (ri < 4) ? (ty * 4 + ri) : (64 + ty * 4 + ri - 4);
                float av = as[r * 20 + k];
                u64 aa = pk2(av, av);
                acc[ri][0] = ffma2(aa, w0, acc[ri][0]);
                acc[ri][1] = ffma2(aa, w1, acc[ri][1]);
                acc[ri][2] = ffma2(aa, w2, acc[ri][2]);
                acc[ri][3] = ffma2(aa, w3, acc[ri][3]);
            }
        }
        __syncthreads();
    }
    #undef PROJ_PREF

    float c[8][8];
    #pragma unroll
    for (int ri = 0; ri < 8; ri++) {
        upk2(acc[ri][0], c[ri][0], c[ri][1]);
        upk2(acc[ri][1], c[ri][2], c[ri][3]);
        upk2(acc[ri][2], c[ri][4], c[ri][5]);
        upk2(acc[ri][3], c[ri][6], c[ri][7]);
    }
    float4 bl = *(const float4*)(bias + col0 + tx * 4);
    float4 bh = *(const float4*)(bias + col0 + 64 + tx * 4);
    float bb[8] = {bl.x, bl.y, bl.z, bl.w, bh.x, bh.y, bh.z, bh.w};

    if (z) {
        #pragma unroll
        for (int ri = 0; ri < 8; ri++) {
            int gr = row0 + ((ri < 4) ? (ty * 4 + ri) : (64 + ty * 4 + ri - 4));
            float4 lo, hi;
            lo.x = c[ri][0] + bb[0]; lo.y = c[ri][1] + bb[1];
            lo.z = c[ri][2] + bb[2]; lo.w = c[ri][3] + bb[3];
            hi.x = c[ri][4] + bb[4]; hi.y = c[ri][5] + bb[5];
            hi.z = c[ri][6] + bb[6]; hi.w = c[ri][7] + bb[7];
            *(float4*)(g_decp + (size_t)gr * 256 + col0 + tx * 4) = lo;
            *(float4*)(g_decp + (size_t)gr * 256 + col0 + 64 + tx * 4) = hi;
        }
    } else {
        const int b  = row0 >> 8;
        const int m0 = row0 & 255;
        const int mA = m0 + ty * 4;
        const int mB = m0 + 64 + ty * 4;
        #pragma unroll
        for (int cj = 0; cj < 8; cj++) {
            int u = col0 + ((cj < 4) ? (tx * 4 + cj) : (64 + tx * 4 + cj - 4));
            float bbv = bb[cj];
            float4 vA, vB;
            vA.x = c[0][cj] + bbv; vA.y = c[1][cj] + bbv;
            vA.z = c[2][cj] + bbv; vA.w = c[3][cj] + bbv;
            vB.x = c[4][cj] + bbv; vB.y = c[5][cj] + bbv;
            vB.z = c[6][cj] + bbv; vB.w = c[7][cj] + bbv;
            *(float4*)(g_encpT + (size_t)b * 65536 + (size_t)u * 256 + mA) = vA;
            *(float4*)(g_encpT + (size_t)b * 65536 + (size_t)u * 256 + mB) = vB;
        }
    }
}

// ---------------------------------------------------------------------------
// Logits + softmax kernel (R7/R13 phase 1+2 verbatim; phase 3 removed).
// Writes softmax weights straight to out_w. smem 41KB.
// Block = 8 n-rows of one b, 512 blocks, 256 threads = 8 warps.
// ---------------------------------------------------------------------------
__global__ __launch_bounds__(256, 4) void logits_kernel(const float* __restrict__ v_w,
                                                        float* __restrict__ out_w)
{
    __shared__ float4 sB[2][1024];    // 2 x 16KB staging
    __shared__ float sD[8 * 256];     // dec_proj rows (8KB)
    __shared__ float sV[256];         // v_w (1KB)
    float* sP = (float*)sB[1];        // alias: partial-exchange buffer (buf1)

    const int tid  = threadIdx.x;
    const int warp = tid >> 5;
    const int lane = tid & 31;
    const int h    = warp >> 2;       // 0: u in [0,128)   1: u in [128,256)
    const int wl   = warp & 3;
    const int r0   = wl * 2;
    const int r1   = r0 + 1;

    const int b  = blockIdx.x >> 5;
    const int n0 = (blockIdx.x & 31) * 8;

    const int pr = tid >> 6;          // prefetch row-group base (0..3)
    const int pc = tid & 63;          // prefetch col

    // stage v and dec_proj tile
    {
        float4* sV4 = (float4*)sV;
        if (tid < 64) sV4[tid] = ((const float4*)v_w)[tid];
        const float4* dsrc = (const float4*)(g_decp + (size_t)(b * NN + n0) * UU);
        float4* sD4 = (float4*)sD;
        sD4[tid] = dsrc[tid];
        sD4[tid + 256] = dsrc[tid + 256];
    }

    const float4* eb4 = (const float4*)(g_encpT + (size_t)b * 65536);

    // chunk s covers rows r=0..15: r<8 -> u=s*8+r; r>=8 -> u=128+s*8+(r-8)
    #define PREFETCH(s, buf)                                                   \
        {                                                                      \
            _Pragma("unroll")                                                  \
            for (int t = 0; t < 4; t++) {                                      \
                int r = pr + t * 4;                                            \
                int u = (s) * 8 + r + ((r < 8) ? 0 : 120);                     \
                cpa16((buf) + r * 64 + pc, eb4 + u * 64 + pc);                 \
            }                                                                  \
        }

    // ---- phase 1: logits (u split across warp halves) ----
    float lg0[8] = {0,0,0,0,0,0,0,0};
    float lg1[8] = {0,0,0,0,0,0,0,0};
    {
        const float* dRow0 = sD + r0 * 256 + h * 128;
        const float* dRow1 = sD + r1 * 256 + h * 128;
        const float* vHalf = sV + h * 128;

        PREFETCH(0, sB[0]);
        CPA_COMMIT;
        for (int s = 0; s < 16; s++) {
            if (s + 1 < 16) PREFETCH(s + 1, sB[(s + 1) & 1]);
            CPA_COMMIT;
            CPA_WAIT1;
            __syncthreads();
            const float4* buf = sB[s & 1];
            #pragma unroll
            for (int j = 0; j < 8; j++) {
                const int ul = s * 8 + j;
                const float dn0 = dRow0[ul];
                const float dn1 = dRow1[ul];
                const float vu  = vHalf[ul];
                float4 ea = buf[(h * 8 + j) * 64 + lane];
                float4 eb = buf[(h * 8 + j) * 64 + 32 + lane];
                lg0[0] = fmaf(vu, tanh_ap(ea.x + dn0), lg0[0]);
                lg0[1] = fmaf(vu, tanh_ap(ea.y + dn0), lg0[1]);
                lg0[2] = fmaf(vu, tanh_ap(ea.z + dn0), lg0[2]);
                lg0[3] = fmaf(vu, tanh_ap(ea.w + dn0), lg0[3]);
                lg0[4] = fmaf(vu, tanh_ap(eb.x + dn0), lg0[4]);
                lg0[5] = fmaf(vu, tanh_ap(eb.y + dn0), lg0[5]);
                lg0[6] = fmaf(vu, tanh_ap(eb.z + dn0), lg0[6]);
                lg0[7] = fmaf(vu, tanh_ap(eb.w + dn0), lg0[7]);
                lg1[0] = fmaf(vu, tanh_ap(ea.x + dn1), lg1[0]);
                lg1[1] = fmaf(vu, tanh_ap(ea.y + dn1), lg1[1]);
                lg1[2] = fmaf(vu, tanh_ap(ea.z + dn1), lg1[2]);
                lg1[3] = fmaf(vu, tanh_ap(ea.w + dn1), lg1[3]);
                lg1[4] = fmaf(vu, tanh_ap(eb.x + dn1), lg1[4]);
                lg1[5] = fmaf(vu, tanh_ap(eb.y + dn1), lg1[5]);
                lg1[6] = fmaf(vu, tanh_ap(eb.z + dn1), lg1[6]);
                lg1[7] = fmaf(vu, tanh_ap(eb.w + dn1), lg1[7]);
            }
            __syncthreads();
        }
    }
    #undef PREFETCH

    // ---- exchange u-partials, softmax (low warps), write weights ----
    if (h == 1) {
        float4* p0 = (float4*)(sP + r0 * 256);
        float4* p1 = (float4*)(sP + r1 * 256);
        p0[lane]      = make_float4(lg0[0], lg0[1], lg0[2], lg0[3]);
        p0[32 + lane] = make_float4(lg0[4], lg0[5], lg0[6], lg0[7]);
        p1[lane]      = make_float4(lg1[0], lg1[1], lg1[2], lg1[3]);
        p1[32 + lane] = make_float4(lg1[4], lg1[5], lg1[6], lg1[7]);
    }
    __syncthreads();
    if (h == 0) {
        {
            float4 q;
            q = ((float4*)(sP + r0 * 256))[lane];
            lg0[0] += q.x; lg0[1] += q.y; lg0[2] += q.z; lg0[3] += q.w;
            q = ((float4*)(sP + r0 * 256))[32 + lane];
            lg0[4] += q.x; lg0[5] += q.y; lg0[6] += q.z; lg0[7] += q.w;
            q = ((float4*)(sP + r1 * 256))[lane];
            lg1[0] += q.x; lg1[1] += q.y; lg1[2] += q.z; lg1[3] += q.w;
            q = ((float4*)(sP + r1 * 256))[32 + lane];
            lg1[4] += q.x; lg1[5] += q.y; lg1[6] += q.z; lg1[7] += q.w;
        }
        #pragma unroll
        for (int r = 0; r < 2; r++) {
            float* lg = r ? lg1 : lg0;
            const int gn = n0 + (r ? r1 : r0);
            float mx = lg[0];
            #pragma unroll
            for (int k = 1; k < 8; k++) mx = fmaxf(mx, lg[k]);
            #pragma unroll
            for (int o = 16; o > 0; o >>= 1) mx = fmaxf(mx, __shfl_xor_sync(0xFFFFFFFFu, mx, o));
            float sum = 0.f;
            #pragma unroll
            for (int k = 0; k < 8; k++) { lg[k] = __expf(lg[k] - mx); sum += lg[k]; }
            #pragma unroll
            for (int o = 16; o > 0; o >>= 1) sum += __shfl_xor_sync(0xFFFFFFFFu, sum, o);
            const float inv = 1.f / sum;

            float4 wA, wB;
            wA.x = lg[0] * inv; wA.y = lg[1] * inv; wA.z = lg[2] * inv; wA.w = lg[3] * inv;
            wB.x = lg[4] * inv; wB.y = lg[5] * inv; wB.z = lg[6] * inv; wB.w = lg[7] * inv;
            float4* wo = (float4*)(out_w + (size_t)(b * NN + gn) * MM);
            wo[lane]      = wA;
            wo[32 + lane] = wB;
        }
    }
}

// ---------------------------------------------------------------------------
// Context GEMM: out_ctx[b] = out_w[b] (256x256, n x m) @ enc[b] (256x256, m x d).
// 64x128 tile, 256 threads, 4x8 microtile, f32x2 FMA, cp.async double-buffered
// BK=16. Grid (2, 4, 16) = 128 blocks (single wave).
// ---------------------------------------------------------------------------
__global__ __launch_bounds__(256) void ctx_gemm(const float* __restrict__ enc,
                                                const float* __restrict__ w_in,
                                                float* __restrict__ out_ctx)
{
    __shared__ float As[2][64 * 20];   // weights tile [n][m-chunk], stride 20
    __shared__ float Bs[2][16 * 128];  // enc tile [m][d]

    const int tid = threadIdx.x;
    const int ty = tid >> 4;
    const int tx = tid & 15;
    const int b  = blockIdx.z;
    const int n0 = blockIdx.y * 64;
    const int d0 = blockIdx.x * 128;

    const float* A = w_in + (size_t)b * 65536;   // [n][m]
    const float* B = enc  + (size_t)b * 65536;   // [m][d]

    u64 acc[4][4] = {};

    #define CTX_PREF(kt, bi)                                                    \
        {                                                                       \
            {                                                                   \
                int r = tid >> 2, kg = tid & 3;                                 \
                cpa16(&As[bi][r * 20 + kg * 4],                                 \
                      A + (size_t)(n0 + r) * 256 + (kt) + kg * 4);              \
            }                                                                   \
            _Pragma("unroll")                                                   \
            for (int i = 0; i < 2; i++) {                                       \
                int fid = tid * 2 + i;                                          \
                int k = fid >> 5, c4 = fid & 31;                                \
                cpa16(&Bs[bi][k * 128 + c4 * 4],                                \
                      B + (size_t)((kt) + k) * 256 + d0 + c4 * 4);              \
            }                                                                   \
        }

    CTX_PREF(0, 0);
    CPA_COMMIT;
    for (int t16 = 0; t16 < 16; t16++) {
        if (t16 + 1 < 16) CTX_PREF((t16 + 1) * 16, (t16 + 1) & 1);
        CPA_COMMIT;
        CPA_WAIT1;
        __syncthreads();
        const float* as = As[t16 & 1];
        const float* bs = Bs[t16 & 1];
        #pragma unroll
        for (int k = 0; k < 16; k++) {
            float4 blo = *(const float4*)(bs + k * 128 + tx * 4);
            float4 bhi = *(const float4*)(bs + k * 128 + 64 + tx * 4);
            u64 w0 = pk2(blo.x, blo.y);
            u64 w1 = pk2(blo.z, blo.w);
            u64 w2 = pk2(bhi.x, bhi.y);
            u64 w3 = pk2(bhi.z, bhi.w);
            #pragma unroll
            for (int ri = 0; ri < 4; ri++) {
                float av = as[(ty * 4 + ri) * 20 + k];
                u64 aa = pk2(av, av);
                acc[ri][0] = ffma2(aa, w0, acc[ri][0]);
                acc[ri][1] = ffma2(aa, w1, acc[ri][1]);
                acc[ri][2] = ffma2(aa, w2, acc[ri][2]);
                acc[ri][3] = ffma2(aa, w3, acc[ri][3]);
            }
        }
        __syncthreads();
    }
    #undef CTX_PREF

    #pragma unroll
    for (int ri = 0; ri < 4; ri++) {
        float4 lo, hi;
        upk2(acc[ri][0], lo.x, lo.y);
        upk2(acc[ri][1], lo.z, lo.w);
        upk2(acc[ri][2], hi.x, hi.y);
        upk2(acc[ri][3], hi.z, hi.w);
        float* dst = out_ctx + (size_t)(b * NN + n0 + ty * 4 + ri) * DD + d0;
        *(float4*)(dst + tx * 4)      = lo;
        *(float4*)(dst + 64 + tx * 4) = hi;
    }
}

extern "C" void kernel_launch(void* const* d_in, const int* in_sizes, int n_in,
                              void* d_out, int out_size)
{
    const float* enc = (const float*)d_in[0];
    const float* dec = (const float*)d_in[1];
    const float* W1  = (const float*)d_in[2];
    const float* b1  = (const float*)d_in[3];
    const float* W2  = (const float*)d_in[4];
    const float* b2  = (const float*)d_in[5];
    const float* vw  = (const float*)d_in[6];
    // d_in[7] = v_b: constant shift, cancels in softmax -> unused.

    float* out_ctx = (float*)d_out;                              // [B,N,D]
    float* out_w   = (float*)d_out + (size_t)Bx * NN * DD;       // [B,N,M,1]

    proj_gemm<<<dim3(2, 32, 2), 256>>>(enc, dec, W1, b1, W2, b2);
    logits_kernel<<<512, 256>>>(vw, out_w);
    ctx_gemm<<<dim3(2, 4, 16), 256>>>(enc, out_w, out_ctx);
}

// round 15
// speedup vs baseline: 1.0887x; 1.0887x over previous
#include <cuda_runtime.h>

#define Bx 16
#define NN 256
#define MM 256
#define DD 256
#define UU 256

typedef unsigned long long u64;

// scratch (device globals — no allocations allowed)
__device__ float g_encpT[Bx * UU * MM];  // enc_proj TRANSPOSED [B][U][M]
__device__ float g_decp [Bx * NN * UU];  // dec_proj [B][N][U]

__device__ __forceinline__ float tanh_ap(float x) {
    float y;
    asm("tanh.approx.f32 %0, %1;" : "=f"(y) : "f"(x));
    return y;
}
__device__ __forceinline__ u64 pk2(float lo, float hi) {
    u64 r;
    asm("mov.b64 %0, {%1, %2};" : "=l"(r) : "f"(lo), "f"(hi));
    return r;
}
__device__ __forceinline__ void upk2(u64 v, float& lo, float& hi) {
    asm("mov.b64 {%0, %1}, %2;" : "=f"(lo), "=f"(hi) : "l"(v));
}
__device__ __forceinline__ u64 ffma2(u64 a, u64 b, u64 c) {
    u64 d;
    asm("fma.rn.f32x2 %0, %1, %2, %3;" : "=l"(d) : "l"(a), "l"(b), "l"(c));
    return d;
}
__device__ __forceinline__ void cpa16(void* smem_dst, const void* gsrc) {
    unsigned sa = (unsigned)__cvta_generic_to_shared(smem_dst);
    asm volatile("cp.async.cg.shared.global [%0], [%1], 16;" :: "r"(sa), "l"(gsrc));
}
#define CPA_COMMIT asm volatile("cp.async.commit_group;")
#define CPA_WAIT1  asm volatile("cp.async.wait_group 1;")

// ---------------------------------------------------------------------------
// Projection GEMM — retiled for occupancy: 128x64 tile, 256 threads, 8x2
// f32x2 microtile (~90 regs), cp.async double-buffered BK=16.
// Grid (4, 32, 2) = 256 blocks (1.73/SM; occupancy-capable 2 blocks/SM).
// z=0: enc@W1+b1 -> g_encpT (transposed [B,U,M]); z=1: dec@W2+b2 -> g_decp.
// ---------------------------------------------------------------------------
__global__ __launch_bounds__(256, 2) void proj_gemm(const float* __restrict__ enc,
                                                    const float* __restrict__ dec,
                                                    const float* __restrict__ W1,
                                                    const float* __restrict__ b1,
                                                    const float* __restrict__ W2,
                                                    const float* __restrict__ b2)
{
    const int z = blockIdx.z;
    const float* A    = z ? dec : enc;
    const float* W    = z ? W2  : W1;
    const float* bias = z ? b2  : b1;

    __shared__ float As[2][128 * 20];   // A tile row-major [r][k], stride 20
    __shared__ float Ws[2][16 * 64];    // W tile row-major [k][c]

    const int tid = threadIdx.x;
    const int ty = tid >> 4;            // 0..15
    const int tx = tid & 15;            // 0..15
    const int row0 = blockIdx.y * 128;
    const int col0 = blockIdx.x * 64;

    u64 acc[8][2] = {};                 // [row 0..7][colpair 0..1]

    #define PROJ_PREF(kt, bi)                                                   \
        {                                                                       \
            _Pragma("unroll")                                                   \
            for (int i = 0; i < 2; i++) {                                       \
                int fid = tid * 2 + i;                                          \
                int r = fid >> 2, kg = fid & 3;                                 \
                cpa16(&As[bi][r * 20 + kg * 4],                                 \
                      A + (size_t)(row0 + r) * 256 + (kt) + kg * 4);            \
            }                                                                   \
            {                                                                   \
                int k = tid >> 4, c4 = tid & 15;                                \
                cpa16(&Ws[bi][k * 64 + c4 * 4],                                 \
                      W + (size_t)((kt) + k) * 256 + col0 + c4 * 4);            \
            }                                                                   \
        }

    PROJ_PREF(0, 0);
    CPA_COMMIT;
    for (int t16 = 0; t16 < 16; t16++) {
        if (t16 + 1 < 16) PROJ_PREF((t16 + 1) * 16, (t16 + 1) & 1);
        CPA_COMMIT;
        CPA_WAIT1;
        __syncthreads();
        const float* as = As[t16 & 1];
        const float* ws = Ws[t16 & 1];
        #pragma unroll
        for (int k = 0; k < 16; k++) {
            float4 wv = *(const float4*)(ws + k * 64 + tx * 4);
            u64 w0 = pk2(wv.x, wv.y);
            u64 w1 = pk2(wv.z, wv.w);
            #pragma unroll
            for (int ri = 0; ri < 8; ri++) {
                int r = (ri < 4) ? (ty * 4 + ri) : (64 + ty * 4 + ri - 4);
                float av = as[r * 20 + k];
                u64 aa = pk2(av, av);
                acc[ri][0] = ffma2(aa, w0, acc[ri][0]);
                acc[ri][1] = ffma2(aa, w1, acc[ri][1]);
            }
        }
        __syncthreads();
    }
    #undef PROJ_PREF

    float c[8][4];
    #pragma unroll
    for (int ri = 0; ri < 8; ri++) {
        upk2(acc[ri][0], c[ri][0], c[ri][1]);
        upk2(acc[ri][1], c[ri][2], c[ri][3]);
    }
    float4 bv = *(const float4*)(bias + col0 + tx * 4);
    float bb[4] = {bv.x, bv.y, bv.z, bv.w};

    if (z) {
        #pragma unroll
        for (int ri = 0; ri < 8; ri++) {
            int gr = row0 + ((ri < 4) ? (ty * 4 + ri) : (64 + ty * 4 + ri - 4));
            float4 o;
            o.x = c[ri][0] + bb[0];
            o.y = c[ri][1] + bb[1];
            o.z = c[ri][2] + bb[2];
            o.w = c[ri][3] + bb[3];
            *(float4*)(g_decp + (size_t)gr * 256 + col0 + tx * 4) = o;
        }
    } else {
        const int b  = row0 >> 8;
        const int m0 = row0 & 255;
        const int mA = m0 + ty * 4;
        const int mB = m0 + 64 + ty * 4;
        #pragma unroll
        for (int cj = 0; cj < 4; cj++) {
            int u = col0 + tx * 4 + cj;
            float bbv = bb[cj];
            float4 vA, vB;
            vA.x = c[0][cj] + bbv; vA.y = c[1][cj] + bbv;
            vA.z = c[2][cj] + bbv; vA.w = c[3][cj] + bbv;
            vB.x = c[4][cj] + bbv; vB.y = c[5][cj] + bbv;
            vB.z = c[6][cj] + bbv; vB.w = c[7][cj] + bbv;
            *(float4*)(g_encpT + (size_t)b * 65536 + (size_t)u * 256 + mA) = vA;
            *(float4*)(g_encpT + (size_t)b * 65536 + (size_t)u * 256 + mB) = vB;
        }
    }
}

// ---------------------------------------------------------------------------
// Fused attention (R13 verbatim — best measured total).
// Phase 1 + softmax: R7 structure (tanh-XU floor). Phase 3: register-direct
// LDG, no barriers. Block = 8 n-rows of one b, 512 blocks, 256 threads.
// ---------------------------------------------------------------------------
__global__ __launch_bounds__(256, 4) void attn_kernel(const float* __restrict__ enc,
                                                      const float* __restrict__ v_w,
                                                      float* __restrict__ out_ctx,
                                                      float* __restrict__ out_w)
{
    __shared__ float4 sB[2][1024];    // 2 x 16KB staging (phase 1 only)
    __shared__ float sD[8 * 256];     // dec_proj rows (8KB)
    __shared__ float sW[8 * 256];     // softmax weights (8KB)
    __shared__ float sV[256];         // v_w (1KB)
    float* sP = (float*)sB[1];        // alias: partial-exchange buffer (buf1)

    const int tid  = threadIdx.x;
    const int warp = tid >> 5;
    const int lane = tid & 31;
    const int h    = warp >> 2;       // 0: axis [0,128)   1: axis [128,256)
    const int wl   = warp & 3;
    const int r0   = wl * 2;
    const int r1   = r0 + 1;

    const int b  = blockIdx.x >> 5;
    const int n0 = (blockIdx.x & 31) * 8;
    const int gn0 = n0 + r0;
    const int gn1 = n0 + r1;

    const int pr = tid >> 6;          // prefetch row-group base (0..3)
    const int pc = tid & 63;          // prefetch col

    // stage v and dec_proj tile
    {
        float4* sV4 = (float4*)sV;
        if (tid < 64) sV4[tid] = ((const float4*)v_w)[tid];
        const float4* dsrc = (const float4*)(g_decp + (size_t)(b * NN + n0) * UU);
        float4* sD4 = (float4*)sD;
        sD4[tid] = dsrc[tid];
        sD4[tid + 256] = dsrc[tid + 256];
    }

    const float4* eb4 = (const float4*)(g_encpT + (size_t)b * 65536);
    const float4* en4 = (const float4*)(enc + (size_t)b * 65536);

    // chunk s covers rows r=0..15: r<8 -> u=s*8+r (low half); r>=8 -> u=128+s*8+(r-8)
    #define PREFETCH(src, s, buf)                                              \
        {                                                                      \
            _Pragma("unroll")                                                  \
            for (int t = 0; t < 4; t++) {                                      \
                int r = pr + t * 4;                                            \
                int u = (s) * 8 + r + ((r < 8) ? 0 : 120);                     \
                cpa16((buf) + r * 64 + pc, (src) + u * 64 + pc);               \
            }                                                                  \
        }

    // ---- phase 1: logits (u split across warp halves) ----
    float lg0[8] = {0,0,0,0,0,0,0,0};
    float lg1[8] = {0,0,0,0,0,0,0,0};
    {
        const float* dRow0 = sD + r0 * 256 + h * 128;
        const float* dRow1 = sD + r1 * 256 + h * 128;
        const float* vHalf = sV + h * 128;

        PREFETCH(eb4, 0, sB[0]);
        CPA_COMMIT;
        for (int s = 0; s < 16; s++) {
            if (s + 1 < 16) PREFETCH(eb4, s + 1, sB[(s + 1) & 1]);
            CPA_COMMIT;
            CPA_WAIT1;
            __syncthreads();
            const float4* buf = sB[s & 1];
            #pragma unroll
            for (int j = 0; j < 8; j++) {
                const int ul = s * 8 + j;
                const float dn0 = dRow0[ul];
                const float dn1 = dRow1[ul];
                const float vu  = vHalf[ul];
                float4 ea = buf[(h * 8 + j) * 64 + lane];
                float4 eb = buf[(h * 8 + j) * 64 + 32 + lane];
                lg0[0] = fmaf(vu, tanh_ap(ea.x + dn0), lg0[0]);
                lg0[1] = fmaf(vu, tanh_ap(ea.y + dn0), lg0[1]);
                lg0[2] = fmaf(vu, tanh_ap(ea.z + dn0), lg0[2]);
                lg0[3] = fmaf(vu, tanh_ap(ea.w + dn0), lg0[3]);
                lg0[4] = fmaf(vu, tanh_ap(eb.x + dn0), lg0[4]);
                lg0[5] = fmaf(vu, tanh_ap(eb.y + dn0), lg0[5]);
                lg0[6] = fmaf(vu, tanh_ap(eb.z + dn0), lg0[6]);
                lg0[7] = fmaf(vu, tanh_ap(eb.w + dn0), lg0[7]);
                lg1[0] = fmaf(vu, tanh_ap(ea.x + dn1), lg1[0]);
                lg1[1] = fmaf(vu, tanh_ap(ea.y + dn1), lg1[1]);
                lg1[2] = fmaf(vu, tanh_ap(ea.z + dn1), lg1[2]);
                lg1[3] = fmaf(vu, tanh_ap(ea.w + dn1), lg1[3]);
                lg1[4] = fmaf(vu, tanh_ap(eb.x + dn1), lg1[4]);
                lg1[5] = fmaf(vu, tanh_ap(eb.y + dn1), lg1[5]);
                lg1[6] = fmaf(vu, tanh_ap(eb.z + dn1), lg1[6]);
                lg1[7] = fmaf(vu, tanh_ap(eb.w + dn1), lg1[7]);
            }
            __syncthreads();
        }
    }

    // ---- exchange u-partials, softmax (low warps), write weights ----
    if (h == 1) {
        float4* p0 = (float4*)(sP + r0 * 256);
        float4* p1 = (float4*)(sP + r1 * 256);
        p0[lane]      = make_float4(lg0[0], lg0[1], lg0[2], lg0[3]);
        p0[32 + lane] = make_float4(lg0[4], lg0[5], lg0[6], lg0[7]);
        p1[lane]      = make_float4(lg1[0], lg1[1], lg1[2], lg1[3]);
        p1[32 + lane] = make_float4(lg1[4], lg1[5], lg1[6], lg1[7]);
    }
    __syncthreads();
    if (h == 0) {
        {
            float4 q;
            q = ((float4*)(sP + r0 * 256))[lane];
            lg0[0] += q.x; lg0[1] += q.y; lg0[2] += q.z; lg0[3] += q.w;
            q = ((float4*)(sP + r0 * 256))[32 + lane];
            lg0[4] += q.x; lg0[5] += q.y; lg0[6] += q.z; lg0[7] += q.w;
            q = ((float4*)(sP + r1 * 256))[lane];
            lg1[0] += q.x; lg1[1] += q.y; lg1[2] += q.z; lg1[3] += q.w;
            q = ((float4*)(sP + r1 * 256))[32 + lane];
            lg1[4] += q.x; lg1[5] += q.y; lg1[6] += q.z; lg1[7] += q.w;
        }
        #pragma unroll
        for (int r = 0; r < 2; r++) {
            float* lg = r ? lg1 : lg0;
            const int ln = r ? r1 : r0;
            const int gn = n0 + ln;
            float mx = lg[0];
            #pragma unroll
            for (int k = 1; k < 8; k++) mx = fmaxf(mx, lg[k]);
            #pragma unroll
            for (int o = 16; o > 0; o >>= 1) mx = fmaxf(mx, __shfl_xor_sync(0xFFFFFFFFu, mx, o));
            float sum = 0.f;
            #pragma unroll
            for (int k = 0; k < 8; k++) { lg[k] = __expf(lg[k] - mx); sum += lg[k]; }
            #pragma unroll
            for (int o = 16; o > 0; o >>= 1) sum += __shfl_xor_sync(0xFFFFFFFFu, sum, o);
            const float inv = 1.f / sum;

            float4 wA, wB;
            wA.x = lg[0] * inv; wA.y = lg[1] * inv; wA.z = lg[2] * inv; wA.w = lg[3] * inv;
            wB.x = lg[4] * inv; wB.y = lg[5] * inv; wB.z = lg[6] * inv; wB.w = lg[7] * inv;
            ((float4*)(sW + ln * 256))[lane]      = wA;
            ((float4*)(sW + ln * 256))[32 + lane] = wB;
            float4* wo = (float4*)(out_w + (size_t)(b * NN + gn) * MM);
            wo[lane]      = wA;
            wo[32 + lane] = wB;
        }
    }
    __syncthreads();

    // ---- phase 3: context — register-direct LDG, no barriers ----
    u64 c0[4] = {0, 0, 0, 0};
    u64 c1[4] = {0, 0, 0, 0};
    {
        const float* w0p = sW + r0 * 256 + h * 128;
        const float* w1p = sW + r1 * 256 + h * 128;
        const float4* ep = en4 + (size_t)(h * 128) * 64;

        #pragma unroll 4
        for (int mi = 0; mi < 128; mi++) {
            float4 ea = ep[mi * 64 + lane];
            float4 eb = ep[mi * 64 + 32 + lane];
            const float w0 = w0p[mi];
            const float w1 = w1p[mi];
            u64 ww0 = pk2(w0, w0);
            u64 ww1 = pk2(w1, w1);
            u64 e0 = pk2(ea.x, ea.y);
            u64 e1 = pk2(ea.z, ea.w);
            u64 e2 = pk2(eb.x, eb.y);
            u64 e3 = pk2(eb.z, eb.w);
            c0[0] = ffma2(ww0, e0, c0[0]);
            c0[1] = ffma2(ww0, e1, c0[1]);
            c0[2] = ffma2(ww0, e2, c0[2]);
            c0[3] = ffma2(ww0, e3, c0[3]);
            c1[0] = ffma2(ww1, e0, c1[0]);
            c1[1] = ffma2(ww1, e1, c1[1]);
            c1[2] = ffma2(ww1, e2, c1[2]);
            c1[3] = ffma2(ww1, e3, c1[3]);
        }
    }

    // ---- exchange m-partials, store context ----
    float4 c0a, c0b, c1a, c1b;
    upk2(c0[0], c0a.x, c0a.y); upk2(c0[1], c0a.z, c0a.w);
    upk2(c0[2], c0b.x, c0b.y); upk2(c0[3], c0b.z, c0b.w);
    upk2(c1[0], c1a.x, c1a.y); upk2(c1[1], c1a.z, c1a.w);
    upk2(c1[2], c1b.x, c1b.y); upk2(c1[3], c1b.z, c1b.w);

    if (h == 1) {
        float4* p0 = (float4*)(sP + r0 * 256);
        float4* p1 = (float4*)(sP + r1 * 256);
        p0[lane]      = c0a;
        p0[32 + lane] = c0b;
        p1[lane]      = c1a;
        p1[32 + lane] = c1b;
    }
    __syncthreads();
    if (h == 0) {
        float4 q;
        q = ((float4*)(sP + r0 * 256))[lane];
        c0a.x += q.x; c0a.y += q.y; c0a.z += q.z; c0a.w += q.w;
        q = ((float4*)(sP + r0 * 256))[32 + lane];
        c0b.x += q.x; c0b.y += q.y; c0b.z += q.z; c0b.w += q.w;
        q = ((float4*)(sP + r1 * 256))[lane];
        c1a.x += q.x; c1a.y += q.y; c1a.z += q.z; c1a.w += q.w;
        q = ((float4*)(sP + r1 * 256))[32 + lane];
        c1b.x += q.x; c1b.y += q.y; c1b.z += q.z; c1b.w += q.w;

        float4* o0 = (float4*)(out_ctx + (size_t)(b * NN + gn0) * DD);
        o0[lane]      = c0a;
        o0[32 + lane] = c0b;
        float4* o1 = (float4*)(out_ctx + (size_t)(b * NN + gn1) * DD);
        o1[lane]      = c1a;
        o1[32 + lane] = c1b;
    }
    #undef PREFETCH
}

extern "C" void kernel_launch(void* const* d_in, const int* in_sizes, int n_in,
                              void* d_out, int out_size)
{
    const float* enc = (const float*)d_in[0];
    const float* dec = (const float*)d_in[1];
    const float* W1  = (const float*)d_in[2];
    const float* b1  = (const float*)d_in[3];
    const float* W2  = (const float*)d_in[4];
    const float* b2  = (const float*)d_in[5];
    const float* vw  = (const float*)d_in[6];
    // d_in[7] = v_b: constant shift, cancels in softmax -> unused.

    float* out_ctx = (float*)d_out;                              // [B,N,D]
    float* out_w   = (float*)d_out + (size_t)Bx * NN * DD;       // [B,N,M,1]

    proj_gemm<<<dim3(4, 32, 2), 256>>>(enc, dec, W1, b1, W2, b2);
    attn_kernel<<<512, 256>>>(enc, vw, out_ctx, out_w);
}